// round 2
// baseline (speedup 1.0000x reference)
#include <cuda_runtime.h>
#include <cstdint>

#define D 128
#define TILE 32
#define NTHREADS 256
#define MAXN 50000

// scratch: aggregated messages per node
__device__ float g_agg[(size_t)MAXN * D];

__device__ __forceinline__ float frelu(float x) { return x > 0.f ? x : 0.f; }

// ---------------------------------------------------------------------------
// init: zero agg, copy coords into output coord region
// ---------------------------------------------------------------------------
__global__ void init_kernel(const float* __restrict__ coords,
                            float* __restrict__ out_coords, int N) {
    int total4 = N * (D / 4);
    for (int i = blockIdx.x * blockDim.x + threadIdx.x; i < total4;
         i += gridDim.x * blockDim.x)
        reinterpret_cast<float4*>(g_agg)[i] = make_float4(0.f, 0.f, 0.f, 0.f);
    int c3 = N * 3;
    for (int i = blockIdx.x * blockDim.x + threadIdx.x; i < c3;
         i += gridDim.x * blockDim.x)
        out_coords[i] = coords[i];
}

// ---------------------------------------------------------------------------
// 4x4 register micro-tile GEMM step over smem input + global weights
//   acc[ee][jj] += sum_k s_in[(e0+ee)*STRIDE + k] * W[k*D + j0+jj]
// ---------------------------------------------------------------------------
template <int K, int STRIDE>
__device__ __forceinline__ void mm_tile(const float* __restrict__ s_in,
                                        const float* __restrict__ W,
                                        int e0, int j0, float acc[4][4]) {
#pragma unroll 4
    for (int k = 0; k < K; ++k) {
        float4 w = __ldg(reinterpret_cast<const float4*>(W + (size_t)k * D + j0));
        float a[4];
#pragma unroll
        for (int ee = 0; ee < 4; ++ee) a[ee] = s_in[(e0 + ee) * STRIDE + k];
#pragma unroll
        for (int ee = 0; ee < 4; ++ee) {
            acc[ee][0] += a[ee] * w.x;
            acc[ee][1] += a[ee] * w.y;
            acc[ee][2] += a[ee] * w.z;
            acc[ee][3] += a[ee] * w.w;
        }
    }
}

__device__ __forceinline__ void load_bias(const float* __restrict__ b, int j0,
                                          float acc[4][4]) {
    float4 bv = __ldg(reinterpret_cast<const float4*>(b + j0));
#pragma unroll
    for (int ee = 0; ee < 4; ++ee) {
        acc[ee][0] = bv.x; acc[ee][1] = bv.y; acc[ee][2] = bv.z; acc[ee][3] = bv.w;
    }
}

// ---------------------------------------------------------------------------
// edge kernel: 32 edges per block
//   smem layout (dynamic):
//     s_ef  [TILE][264]  (cols 0..256 = [h_row | h_col | dist2]); later aliased
//                         as s_msg [TILE][132]
//     s_hid [TILE][132]
//     s_rel [TILE][4]
//     s_row [TILE] (int)
// ---------------------------------------------------------------------------
#define EF_STRIDE 264
#define HID_STRIDE 132
#define EDGE_SMEM_FLOATS (TILE * EF_STRIDE + TILE * HID_STRIDE + TILE * 4)
#define EDGE_SMEM_BYTES (EDGE_SMEM_FLOATS * 4 + TILE * 4)

__global__ void edge_kernel(const float* __restrict__ h,
                            const float* __restrict__ coords,
                            const int* __restrict__ ei,
                            const float* __restrict__ We1, const float* __restrict__ be1,
                            const float* __restrict__ We2, const float* __restrict__ be2,
                            const float* __restrict__ Wc1, const float* __restrict__ bc1,
                            const float* __restrict__ Wc2,
                            float* __restrict__ out_coords,
                            int E) {
    extern __shared__ float smem[];
    float* s_ef = smem;                          // [TILE][264]
    float* s_hid = smem + TILE * EF_STRIDE;      // [TILE][132]
    float* s_msg = s_ef;                         // alias, [TILE][132]
    float* s_rel = s_hid + TILE * HID_STRIDE;    // [TILE][4]
    int* s_row = reinterpret_cast<int*>(s_rel + TILE * 4);

    const int tid = threadIdx.x;
    const int e_base = blockIdx.x * TILE;

    // per-edge scalars: rel coords, dist2, row index
    if (tid < TILE) {
        int ge = e_base + tid;
        int r = 0, c = 0;
        if (ge < E) {
            r = ei[ge];
            c = ei[E + ge];
        }
        s_row[tid] = r;
        float rx = coords[r * 3 + 0] - coords[c * 3 + 0];
        float ry = coords[r * 3 + 1] - coords[c * 3 + 1];
        float rz = coords[r * 3 + 2] - coords[c * 3 + 2];
        s_rel[tid * 4 + 0] = rx;
        s_rel[tid * 4 + 1] = ry;
        s_rel[tid * 4 + 2] = rz;
        s_ef[tid * EF_STRIDE + 256] = rx * rx + ry * ry + rz * rz;
    }

    // gather h[row], h[col] (float4, coalesced per edge row)
    for (int idx = tid; idx < TILE * 32; idx += NTHREADS) {
        int e = idx >> 5, k4 = idx & 31;
        int ge = e_base + e;
        float4 hr = make_float4(0.f, 0.f, 0.f, 0.f), hc = hr;
        if (ge < E) {
            int r = ei[ge];
            int c = ei[E + ge];
            hr = *reinterpret_cast<const float4*>(h + (size_t)r * D + k4 * 4);
            hc = *reinterpret_cast<const float4*>(h + (size_t)c * D + k4 * 4);
        }
        *reinterpret_cast<float4*>(s_ef + e * EF_STRIDE + k4 * 4) = hr;
        *reinterpret_cast<float4*>(s_ef + e * EF_STRIDE + 128 + k4 * 4) = hc;
    }
    __syncthreads();

    const int fe = tid & 31, eg = tid >> 5;
    const int j0 = fe * 4, e0 = eg * 4;

    // ---- layer 1: hid = relu(ef @ We1 + be1), K = 257 ----
    {
        float acc[4][4];
        load_bias(be1, j0, acc);
        mm_tile<257, EF_STRIDE>(s_ef, We1, e0, j0, acc);
#pragma unroll
        for (int ee = 0; ee < 4; ++ee)
#pragma unroll
            for (int jj = 0; jj < 4; ++jj)
                s_hid[(e0 + ee) * HID_STRIDE + j0 + jj] = frelu(acc[ee][jj]);
    }
    __syncthreads();

    // ---- layer 2: msg = hid @ We2 + be2, K = 128 (overwrites s_ef region) ----
    {
        float acc[4][4];
        load_bias(be2, j0, acc);
        mm_tile<128, HID_STRIDE>(s_hid, We2, e0, j0, acc);
#pragma unroll
        for (int ee = 0; ee < 4; ++ee)
#pragma unroll
            for (int jj = 0; jj < 4; ++jj)
                s_msg[(e0 + ee) * HID_STRIDE + j0 + jj] = acc[ee][jj];
    }
    __syncthreads();

    // ---- coord head: w = relu(msg @ Wc1 + bc1) @ Wc2, fused ----
    {
        float acc[4][4];
        load_bias(bc1, j0, acc);
        mm_tile<128, HID_STRIDE>(s_msg, Wc1, e0, j0, acc);
        float4 c2 = __ldg(reinterpret_cast<const float4*>(Wc2 + j0));
        float ws[4];
#pragma unroll
        for (int ee = 0; ee < 4; ++ee)
            ws[ee] = frelu(acc[ee][0]) * c2.x + frelu(acc[ee][1]) * c2.y +
                     frelu(acc[ee][2]) * c2.z + frelu(acc[ee][3]) * c2.w;
        // warp holds one 4-edge group across its 32 lanes -> shuffle reduce
#pragma unroll
        for (int off = 16; off; off >>= 1)
#pragma unroll
            for (int ee = 0; ee < 4; ++ee)
                ws[ee] += __shfl_xor_sync(0xffffffffu, ws[ee], off);
        if (fe == 0) {
#pragma unroll
            for (int ee = 0; ee < 4; ++ee) {
                int e = e0 + ee;
                if (e_base + e < E) {
                    float w = ws[ee];
                    int r = s_row[e];
                    atomicAdd(out_coords + r * 3 + 0, w * s_rel[e * 4 + 0]);
                    atomicAdd(out_coords + r * 3 + 1, w * s_rel[e * 4 + 1]);
                    atomicAdd(out_coords + r * 3 + 2, w * s_rel[e * 4 + 2]);
                }
            }
        }
    }

    // ---- message scatter-add (coalesced along feature dim) ----
    for (int idx = tid; idx < TILE * D; idx += NTHREADS) {
        int e = idx >> 7, j = idx & 127;
        if (e_base + e < E)
            atomicAdd(g_agg + (size_t)s_row[e] * D + j, s_msg[e * HID_STRIDE + j]);
    }
}

// ---------------------------------------------------------------------------
// node kernel: h_new = relu([h, agg] @ Wn1 + bn1) @ Wn2 + bn2
// ---------------------------------------------------------------------------
#define NODE_SMEM_BYTES ((TILE * EF_STRIDE + TILE * HID_STRIDE) * 4)

__global__ void node_kernel(const float* __restrict__ h,
                            const float* __restrict__ Wn1, const float* __restrict__ bn1,
                            const float* __restrict__ Wn2, const float* __restrict__ bn2,
                            float* __restrict__ out_h, int N) {
    extern __shared__ float smem[];
    float* s_in = smem;                      // [TILE][264], cols 0..255
    float* s_hid = smem + TILE * EF_STRIDE;  // [TILE][132]

    const int tid = threadIdx.x;
    const int r_base = blockIdx.x * TILE;

    for (int idx = tid; idx < TILE * 32; idx += NTHREADS) {
        int e = idx >> 5, k4 = idx & 31;
        int row = r_base + e;
        float4 a = make_float4(0.f, 0.f, 0.f, 0.f), b = a;
        if (row < N) {
            a = *reinterpret_cast<const float4*>(h + (size_t)row * D + k4 * 4);
            b = *reinterpret_cast<const float4*>(g_agg + (size_t)row * D + k4 * 4);
        }
        *reinterpret_cast<float4*>(s_in + e * EF_STRIDE + k4 * 4) = a;
        *reinterpret_cast<float4*>(s_in + e * EF_STRIDE + 128 + k4 * 4) = b;
    }
    __syncthreads();

    const int fe = tid & 31, eg = tid >> 5;
    const int j0 = fe * 4, e0 = eg * 4;

    {
        float acc[4][4];
        load_bias(bn1, j0, acc);
        mm_tile<256, EF_STRIDE>(s_in, Wn1, e0, j0, acc);
#pragma unroll
        for (int ee = 0; ee < 4; ++ee)
#pragma unroll
            for (int jj = 0; jj < 4; ++jj)
                s_hid[(e0 + ee) * HID_STRIDE + j0 + jj] = frelu(acc[ee][jj]);
    }
    __syncthreads();

    {
        float acc[4][4];
        load_bias(bn2, j0, acc);
        mm_tile<128, HID_STRIDE>(s_hid, Wn2, e0, j0, acc);
#pragma unroll
        for (int ee = 0; ee < 4; ++ee) {
            int row = r_base + e0 + ee;
            if (row < N)
                *reinterpret_cast<float4*>(out_h + (size_t)row * D + j0) =
                    make_float4(acc[ee][0], acc[ee][1], acc[ee][2], acc[ee][3]);
        }
    }
}

// ---------------------------------------------------------------------------
// launch
// ---------------------------------------------------------------------------
extern "C" void kernel_launch(void* const* d_in, const int* in_sizes, int n_in,
                              void* d_out, int out_size) {
    const float* h = (const float*)d_in[0];
    const float* coords = (const float*)d_in[1];
    const int* ei = (const int*)d_in[2];
    const float* We1 = (const float*)d_in[3];
    const float* be1 = (const float*)d_in[4];
    const float* We2 = (const float*)d_in[5];
    const float* be2 = (const float*)d_in[6];
    const float* Wn1 = (const float*)d_in[7];
    const float* bn1 = (const float*)d_in[8];
    const float* Wn2 = (const float*)d_in[9];
    const float* bn2 = (const float*)d_in[10];
    const float* Wc1 = (const float*)d_in[11];
    const float* bc1 = (const float*)d_in[12];
    const float* Wc2 = (const float*)d_in[13];

    int N = in_sizes[0] / D;
    int E = in_sizes[2] / 2;

    float* out_h = (float*)d_out;
    float* out_coords = out_h + (size_t)N * D;

    cudaFuncSetAttribute(edge_kernel, cudaFuncAttributeMaxDynamicSharedMemorySize,
                         EDGE_SMEM_BYTES);
    cudaFuncSetAttribute(node_kernel, cudaFuncAttributeMaxDynamicSharedMemorySize,
                         NODE_SMEM_BYTES);

    init_kernel<<<1184, 256>>>(coords, out_coords, N);

    int edge_blocks = (E + TILE - 1) / TILE;
    edge_kernel<<<edge_blocks, NTHREADS, EDGE_SMEM_BYTES>>>(
        h, coords, ei, We1, be1, We2, be2, Wc1, bc1, Wc2, out_coords, E);

    int node_blocks = (N + TILE - 1) / TILE;
    node_kernel<<<node_blocks, NTHREADS, NODE_SMEM_BYTES>>>(
        h, Wn1, bn1, Wn2, bn2, out_h, N);
}

// round 3
// speedup vs baseline: 1.0113x; 1.0113x over previous
#include <cuda_runtime.h>
#include <cstdint>

#define D 128
#define TILE 32
#define NTHREADS 256
#define MAXN 50000

typedef unsigned long long u64;

// scratch: aggregated messages per node
__device__ float g_agg[(size_t)MAXN * D];

__device__ __forceinline__ float frelu(float x) { return x > 0.f ? x : 0.f; }

__device__ __forceinline__ u64 pack2(float lo, float hi) {
    u64 r;
    asm("mov.b64 %0, {%1, %2};" : "=l"(r) : "r"(__float_as_uint(lo)), "r"(__float_as_uint(hi)));
    return r;
}
__device__ __forceinline__ u64 bcast2(float v) {
    u64 r;
    asm("mov.b64 %0, {%1, %1};" : "=l"(r) : "r"(__float_as_uint(v)));
    return r;
}
__device__ __forceinline__ void unpack2(u64 v, float& lo, float& hi) {
    unsigned int l, h;
    asm("mov.b64 {%0, %1}, %2;" : "=r"(l), "=r"(h) : "l"(v));
    lo = __uint_as_float(l);
    hi = __uint_as_float(h);
}
__device__ __forceinline__ void fma2(u64& acc, u64 a, u64 b) {
    asm("fma.rn.f32x2 %0, %1, %2, %0;" : "+l"(acc) : "l"(a), "l"(b));
}

// ---------------------------------------------------------------------------
// init: zero agg, copy coords into output coord region
// ---------------------------------------------------------------------------
__global__ void init_kernel(const float* __restrict__ coords,
                            float* __restrict__ out_coords, int N) {
    int total4 = N * (D / 4);
    for (int i = blockIdx.x * blockDim.x + threadIdx.x; i < total4;
         i += gridDim.x * blockDim.x)
        reinterpret_cast<float4*>(g_agg)[i] = make_float4(0.f, 0.f, 0.f, 0.f);
    int c3 = N * 3;
    for (int i = blockIdx.x * blockDim.x + threadIdx.x; i < c3;
         i += gridDim.x * blockDim.x)
        out_coords[i] = coords[i];
}

// ---------------------------------------------------------------------------
// 4x4 register micro-tile GEMM step, f32x2-packed over the j (feature) dim.
//   acc0[ee] holds (j0, j0+1), acc1[ee] holds (j0+2, j0+3)
// ---------------------------------------------------------------------------
template <int K, int STRIDE>
__device__ __forceinline__ void mm_tile2(const float* __restrict__ s_in,
                                         const float* __restrict__ W,
                                         int e0, int j0,
                                         u64 acc0[4], u64 acc1[4]) {
#pragma unroll 4
    for (int k = 0; k < K; ++k) {
        ulonglong2 w = __ldg(reinterpret_cast<const ulonglong2*>(W + (size_t)k * D + j0));
#pragma unroll
        for (int ee = 0; ee < 4; ++ee) {
            u64 ap = bcast2(s_in[(e0 + ee) * STRIDE + k]);
            fma2(acc0[ee], ap, w.x);
            fma2(acc1[ee], ap, w.y);
        }
    }
}

__device__ __forceinline__ void load_bias2(const float* __restrict__ b, int j0,
                                           u64 acc0[4], u64 acc1[4]) {
    float4 bv = __ldg(reinterpret_cast<const float4*>(b + j0));
    u64 b0 = pack2(bv.x, bv.y), b1 = pack2(bv.z, bv.w);
#pragma unroll
    for (int ee = 0; ee < 4; ++ee) {
        acc0[ee] = b0;
        acc1[ee] = b1;
    }
}

// ---------------------------------------------------------------------------
// edge kernel: 32 edges per block
// ---------------------------------------------------------------------------
#define EF_STRIDE 264
#define HID_STRIDE 132
#define EDGE_SMEM_FLOATS (TILE * EF_STRIDE + TILE * HID_STRIDE + TILE * 4)
#define EDGE_SMEM_BYTES (EDGE_SMEM_FLOATS * 4 + TILE * 4)

__global__ void edge_kernel(const float* __restrict__ h,
                            const float* __restrict__ coords,
                            const int* __restrict__ ei,
                            const float* __restrict__ We1, const float* __restrict__ be1,
                            const float* __restrict__ We2, const float* __restrict__ be2,
                            const float* __restrict__ Wc1, const float* __restrict__ bc1,
                            const float* __restrict__ Wc2,
                            float* __restrict__ out_coords,
                            int E) {
    extern __shared__ float smem[];
    float* s_ef = smem;                          // [TILE][264]
    float* s_hid = smem + TILE * EF_STRIDE;      // [TILE][132]
    float* s_msg = s_ef;                         // alias, [TILE][132]
    float* s_rel = s_hid + TILE * HID_STRIDE;    // [TILE][4]
    int* s_row = reinterpret_cast<int*>(s_rel + TILE * 4);

    const int tid = threadIdx.x;
    const int e_base = blockIdx.x * TILE;

    // per-edge scalars: rel coords, dist2, row index
    if (tid < TILE) {
        int ge = e_base + tid;
        int r = 0, c = 0;
        if (ge < E) {
            r = ei[ge];
            c = ei[E + ge];
        }
        s_row[tid] = r;
        float rx = coords[r * 3 + 0] - coords[c * 3 + 0];
        float ry = coords[r * 3 + 1] - coords[c * 3 + 1];
        float rz = coords[r * 3 + 2] - coords[c * 3 + 2];
        s_rel[tid * 4 + 0] = rx;
        s_rel[tid * 4 + 1] = ry;
        s_rel[tid * 4 + 2] = rz;
        s_ef[tid * EF_STRIDE + 256] = rx * rx + ry * ry + rz * rz;
    }

    // gather h[row], h[col] (float4, coalesced per edge row)
    for (int idx = tid; idx < TILE * 32; idx += NTHREADS) {
        int e = idx >> 5, k4 = idx & 31;
        int ge = e_base + e;
        float4 hr = make_float4(0.f, 0.f, 0.f, 0.f), hc = hr;
        if (ge < E) {
            int r = ei[ge];
            int c = ei[E + ge];
            hr = *reinterpret_cast<const float4*>(h + (size_t)r * D + k4 * 4);
            hc = *reinterpret_cast<const float4*>(h + (size_t)c * D + k4 * 4);
        }
        *reinterpret_cast<float4*>(s_ef + e * EF_STRIDE + k4 * 4) = hr;
        *reinterpret_cast<float4*>(s_ef + e * EF_STRIDE + 128 + k4 * 4) = hc;
    }
    __syncthreads();

    const int fe = tid & 31, eg = tid >> 5;
    const int j0 = fe * 4, e0 = eg * 4;

    // ---- layer 1: hid = relu(ef @ We1 + be1), K = 257 ----
    {
        u64 acc0[4], acc1[4];
        load_bias2(be1, j0, acc0, acc1);
        mm_tile2<257, EF_STRIDE>(s_ef, We1, e0, j0, acc0, acc1);
#pragma unroll
        for (int ee = 0; ee < 4; ++ee) {
            float v0, v1, v2, v3;
            unpack2(acc0[ee], v0, v1);
            unpack2(acc1[ee], v2, v3);
            float* dst = s_hid + (e0 + ee) * HID_STRIDE + j0;
            dst[0] = frelu(v0); dst[1] = frelu(v1);
            dst[2] = frelu(v2); dst[3] = frelu(v3);
        }
    }
    __syncthreads();

    // ---- layer 2: msg = hid @ We2 + be2, K = 128 (overwrites s_ef region) ----
    {
        u64 acc0[4], acc1[4];
        load_bias2(be2, j0, acc0, acc1);
        mm_tile2<128, HID_STRIDE>(s_hid, We2, e0, j0, acc0, acc1);
#pragma unroll
        for (int ee = 0; ee < 4; ++ee) {
            float v0, v1, v2, v3;
            unpack2(acc0[ee], v0, v1);
            unpack2(acc1[ee], v2, v3);
            float* dst = s_msg + (e0 + ee) * HID_STRIDE + j0;
            dst[0] = v0; dst[1] = v1; dst[2] = v2; dst[3] = v3;
        }
    }
    __syncthreads();

    // ---- coord head: w = relu(msg @ Wc1 + bc1) @ Wc2, fused ----
    {
        u64 acc0[4], acc1[4];
        load_bias2(bc1, j0, acc0, acc1);
        mm_tile2<128, HID_STRIDE>(s_msg, Wc1, e0, j0, acc0, acc1);
        float4 c2 = __ldg(reinterpret_cast<const float4*>(Wc2 + j0));
        float ws[4];
#pragma unroll
        for (int ee = 0; ee < 4; ++ee) {
            float v0, v1, v2, v3;
            unpack2(acc0[ee], v0, v1);
            unpack2(acc1[ee], v2, v3);
            ws[ee] = frelu(v0) * c2.x + frelu(v1) * c2.y +
                     frelu(v2) * c2.z + frelu(v3) * c2.w;
        }
        // warp holds one 4-edge group across its 32 lanes -> shuffle reduce
#pragma unroll
        for (int off = 16; off; off >>= 1)
#pragma unroll
            for (int ee = 0; ee < 4; ++ee)
                ws[ee] += __shfl_xor_sync(0xffffffffu, ws[ee], off);
        if (fe == 0) {
#pragma unroll
            for (int ee = 0; ee < 4; ++ee) {
                int e = e0 + ee;
                if (e_base + e < E) {
                    float w = ws[ee];
                    int r = s_row[e];
                    atomicAdd(out_coords + r * 3 + 0, w * s_rel[e * 4 + 0]);
                    atomicAdd(out_coords + r * 3 + 1, w * s_rel[e * 4 + 1]);
                    atomicAdd(out_coords + r * 3 + 2, w * s_rel[e * 4 + 2]);
                }
            }
        }
    }

    // ---- message scatter-add (coalesced along feature dim) ----
    for (int idx = tid; idx < TILE * D; idx += NTHREADS) {
        int e = idx >> 7, j = idx & 127;
        if (e_base + e < E)
            atomicAdd(g_agg + (size_t)s_row[e] * D + j, s_msg[e * HID_STRIDE + j]);
    }
}

// ---------------------------------------------------------------------------
// node kernel: h_new = relu([h, agg] @ Wn1 + bn1) @ Wn2 + bn2
// ---------------------------------------------------------------------------
#define NODE_SMEM_BYTES ((TILE * EF_STRIDE + TILE * HID_STRIDE) * 4)

__global__ void node_kernel(const float* __restrict__ h,
                            const float* __restrict__ Wn1, const float* __restrict__ bn1,
                            const float* __restrict__ Wn2, const float* __restrict__ bn2,
                            float* __restrict__ out_h, int N) {
    extern __shared__ float smem[];
    float* s_in = smem;                      // [TILE][264], cols 0..255
    float* s_hid = smem + TILE * EF_STRIDE;  // [TILE][132]

    const int tid = threadIdx.x;
    const int r_base = blockIdx.x * TILE;

    for (int idx = tid; idx < TILE * 32; idx += NTHREADS) {
        int e = idx >> 5, k4 = idx & 31;
        int row = r_base + e;
        float4 a = make_float4(0.f, 0.f, 0.f, 0.f), b = a;
        if (row < N) {
            a = *reinterpret_cast<const float4*>(h + (size_t)row * D + k4 * 4);
            b = *reinterpret_cast<const float4*>(g_agg + (size_t)row * D + k4 * 4);
        }
        *reinterpret_cast<float4*>(s_in + e * EF_STRIDE + k4 * 4) = a;
        *reinterpret_cast<float4*>(s_in + e * EF_STRIDE + 128 + k4 * 4) = b;
    }
    __syncthreads();

    const int fe = tid & 31, eg = tid >> 5;
    const int j0 = fe * 4, e0 = eg * 4;

    {
        u64 acc0[4], acc1[4];
        load_bias2(bn1, j0, acc0, acc1);
        mm_tile2<256, EF_STRIDE>(s_in, Wn1, e0, j0, acc0, acc1);
#pragma unroll
        for (int ee = 0; ee < 4; ++ee) {
            float v0, v1, v2, v3;
            unpack2(acc0[ee], v0, v1);
            unpack2(acc1[ee], v2, v3);
            float* dst = s_hid + (e0 + ee) * HID_STRIDE + j0;
            dst[0] = frelu(v0); dst[1] = frelu(v1);
            dst[2] = frelu(v2); dst[3] = frelu(v3);
        }
    }
    __syncthreads();

    {
        u64 acc0[4], acc1[4];
        load_bias2(bn2, j0, acc0, acc1);
        mm_tile2<128, HID_STRIDE>(s_hid, Wn2, e0, j0, acc0, acc1);
#pragma unroll
        for (int ee = 0; ee < 4; ++ee) {
            int row = r_base + e0 + ee;
            if (row < N) {
                float v0, v1, v2, v3;
                unpack2(acc0[ee], v0, v1);
                unpack2(acc1[ee], v2, v3);
                *reinterpret_cast<float4*>(out_h + (size_t)row * D + j0) =
                    make_float4(v0, v1, v2, v3);
            }
        }
    }
}

// ---------------------------------------------------------------------------
// launch
// ---------------------------------------------------------------------------
extern "C" void kernel_launch(void* const* d_in, const int* in_sizes, int n_in,
                              void* d_out, int out_size) {
    const float* h = (const float*)d_in[0];
    const float* coords = (const float*)d_in[1];
    const int* ei = (const int*)d_in[2];
    const float* We1 = (const float*)d_in[3];
    const float* be1 = (const float*)d_in[4];
    const float* We2 = (const float*)d_in[5];
    const float* be2 = (const float*)d_in[6];
    const float* Wn1 = (const float*)d_in[7];
    const float* bn1 = (const float*)d_in[8];
    const float* Wn2 = (const float*)d_in[9];
    const float* bn2 = (const float*)d_in[10];
    const float* Wc1 = (const float*)d_in[11];
    const float* bc1 = (const float*)d_in[12];
    const float* Wc2 = (const float*)d_in[13];

    int N = in_sizes[0] / D;
    int E = in_sizes[2] / 2;

    float* out_h = (float*)d_out;
    float* out_coords = out_h + (size_t)N * D;

    cudaFuncSetAttribute(edge_kernel, cudaFuncAttributeMaxDynamicSharedMemorySize,
                         EDGE_SMEM_BYTES);
    cudaFuncSetAttribute(node_kernel, cudaFuncAttributeMaxDynamicSharedMemorySize,
                         NODE_SMEM_BYTES);

    init_kernel<<<1184, 256>>>(coords, out_coords, N);

    int edge_blocks = (E + TILE - 1) / TILE;
    edge_kernel<<<edge_blocks, NTHREADS, EDGE_SMEM_BYTES>>>(
        h, coords, ei, We1, be1, We2, be2, Wc1, bc1, Wc2, out_coords, E);

    int node_blocks = (N + TILE - 1) / TILE;
    node_kernel<<<node_blocks, NTHREADS, NODE_SMEM_BYTES>>>(
        h, Wn1, bn1, Wn2, bn2, out_h, N);
}